// round 15
// baseline (speedup 1.0000x reference)
#include <cuda_runtime.h>
#include <cuda_bf16.h>
#include <cstdint>

#define NG   32
#define NPG  1024
#define NN   (NG*NPG)
#define HD   128
#define NLAY 4
#define NPAR 256
#define NPT  (NG*NPAR)
#define NCLS 50
#define DCCN 16
#define CS   (DCCN*NCLS)   // 800

typedef unsigned long long u64t;

__device__ __forceinline__ u64t pk2(float x, float y){ u64t r; asm("mov.b64 %0, {%1,%2};" : "=l"(r) : "f"(x), "f"(y)); return r; }
__device__ __forceinline__ void upk2(u64t p, float& x, float& y){ asm("mov.b64 {%0,%1}, %2;" : "=f"(x), "=f"(y) : "l"(p)); }
__device__ __forceinline__ u64t fma2_(u64t a, u64t b, u64t c){ u64t d; asm("fma.rn.f32x2 %0, %1, %2, %3;" : "=l"(d) : "l"(a), "l"(b), "l"(c)); return d; }
__device__ __forceinline__ u64t mul2_(u64t a, u64t b){ u64t d; asm("mul.rn.f32x2 %0, %1, %2;" : "=l"(d) : "l"(a), "l"(b)); return d; }
__device__ __forceinline__ u64t add2_(u64t a, u64t b){ u64t d; asm("add.rn.f32x2 %0, %1, %2;" : "=l"(d) : "l"(a), "l"(b)); return d; }

__device__ __forceinline__ void cluster_sync_fenced(){
    __threadfence();
    asm volatile("barrier.cluster.arrive.aligned;" ::: "memory");
    asm volatile("barrier.cluster.wait.aligned;" ::: "memory");
}

// ---------------- device scratch ----------------
__device__ __align__(256) float g_h0[NN*HD];
__device__ __align__(256) float g_f0[NN*HD];
__device__ __align__(256) float g_f1[NN*HD];
__device__ __align__(256) float g_f2[NN*HD];
__device__ __align__(256) float g_f3[NN*HD];
__device__ __align__(256) float g_l2[NN];
__device__ __align__(256) float g_u  [NN*4];
__device__ __align__(256) float g_Vc0[NN*4];
__device__ __align__(256) float g_Vc1[NN*4];
__device__ __align__(256) float g_pM [NN];
__device__ __align__(256) float g_pZ [NN];
__device__ __align__(256) float g_aP [NN*4];
__device__ __align__(256) float g_SC [NN*4];
__device__ __align__(256) float g_delta[NN*NCLS];
__device__ __align__(256) float g_gamma[NN*NCLS];
__device__ __align__(256) float g_zs[3*NG*CS];   // [r][b][s][c]  (c contiguous)
__device__ __align__(256) float g_z [NG*CS];     // [b][s][c]

__device__ __forceinline__ float* featptr(int l){
    switch(l){ case 0: return g_f0; case 1: return g_f1; case 2: return g_f2; default: return g_f3; }
}

// smem overlay macros (one 64000-byte buffer)
#define GLX(b,k,p)   smf[(((b)*16+(k))*36+(p))]
#define GRX(b,k,p)   smf[(4608/4) + (((b)*16+(k))*36+(p))]
#define XSS(b,k,p)   smf[(9216/4) + (((b)*16+(k))*36+(p))]
#define WS3(b,s,k,c) smf[(13824/4) + ((((b)*3+(s))*16+(k))*128+(c))]

// ================= MEGA: embed + 4 GEMM layers + top8 + VTS (per-graph clusters) ==========
__global__ __launch_bounds__(256) __cluster_dims__(1,8,1) void k_mega(
    const int* __restrict__ type_ids, const int* __restrict__ token_ids,
    const float* __restrict__ temb, const float* __restrict__ kemb,
    const float* __restrict__ WLp, const float* __restrict__ WRp,
    const float* __restrict__ WTp, const float* __restrict__ bconv,
    const float* __restrict__ lw, const float* __restrict__ rw){
    __shared__ __align__(16) char smraw[64000];
    float* smf = (float*)smraw;
    float* lw_s = (float*)(smraw + 62976);
    float* rw_s = (float*)(smraw + 63488);

    const int g = blockIdx.x, y = blockIdx.y, tid = threadIdx.x;
    const int lane = tid & 31;

    // ---- zero zs ----
    for (int i = (g*8+y)*256 + tid; i < 3*NG*CS; i += 256*256) g_zs[i] = 0.f;

    // ---- embed phase: nodes [g*1024 + y*128, +128) ----
    for (int i = tid; i < 4096; i += 256){
        int local = y*128 + (i>>5);
        int n = g*NPG + local;
        int q = i & 31;
        float4 v;
        if (q < 16) v = *(const float4*)(temb + (size_t)type_ids[n]*64 + q*4);
        else        v = *(const float4*)(kemb + (size_t)token_ids[n]*64 + (q-16)*4);
        *(float4*)(g_h0 + (size_t)n*HD + q*4) = v;
        bool leaf = local >= NPAR;
        float sq = v.x*v.x + v.y*v.y + v.z*v.z + v.w*v.w;
        #pragma unroll
        for (int s=16;s;s>>=1) sq += __shfl_xor_sync(0xffffffffu, sq, s);
        if (q == 0) g_l2[n] = leaf ? 4.f*sq : 0.f;
    }
    cluster_sync_fenced();

    // ---- GEMM phase ----
    const int l0 = y*32;
    const int rgrp = tid >> 5;
    const int tx   = tid & 31;
    const int p_rel = tid >> 2, q4 = tid & 3;
    const bool stg = tid < 128;

    if (stg){
        int e_local = 4*l0 + tid;
        bool valid = e_local < 1023;
        lw_s[tid] = valid ? lw[g*1023 + e_local] : 0.f;
        rw_s[tid] = valid ? rw[g*1023 + e_local] : 0.f;
    }
    __syncthreads();

    int cloc[4];
    #pragma unroll
    for (int j=0;j<4;j++){
        int c_local = 4*(l0+p_rel) + 1 + j;
        if (c_local > 1023) c_local = 1023;
        cloc[j] = c_local;
    }

    #pragma unroll 1
    for (int layer = 0; layer < NLAY; layer++){
        const float* hin = (layer==0) ? g_h0 : featptr(layer-1);
        const float* Wb[3] = { WLp + layer*HD*HD, WRp + layer*HD*HD, WTp + layer*HD*HD };
        float4 pW[6];
        float4 par, ch0, ch1, ch2, ch3;

        auto do_prefetch = [&](int k0){
            #pragma unroll
            for (int i=0;i<6;i++){
                int qq = tid + i*256;
                int seg = qq >> 9, r = qq & 511;
                int k = r >> 5, n4 = r & 31;
                pW[i] = *(const float4*)(Wb[seg] + (size_t)(k0+k)*HD + n4*4);
            }
            if (stg){
                par = *(const float4*)(hin + (size_t)(g*NPG + l0 + p_rel)*HD + k0 + q4*4);
                const float* c0s = (cloc[0] < NPAR) ? hin : g_h0;
                const float* c1s = (cloc[1] < NPAR) ? hin : g_h0;
                const float* c2s = (cloc[2] < NPAR) ? hin : g_h0;
                const float* c3s = (cloc[3] < NPAR) ? hin : g_h0;
                ch0 = *(const float4*)(c0s + (size_t)(g*NPG + cloc[0])*HD + k0 + q4*4);
                ch1 = *(const float4*)(c1s + (size_t)(g*NPG + cloc[1])*HD + k0 + q4*4);
                ch2 = *(const float4*)(c2s + (size_t)(g*NPG + cloc[2])*HD + k0 + q4*4);
                ch3 = *(const float4*)(c3s + (size_t)(g*NPG + cloc[3])*HD + k0 + q4*4);
            }
        };
        auto do_commit = [&](int buf){
            #pragma unroll
            for (int i=0;i<6;i++){
                int qq = tid + i*256;
                int seg = qq >> 9, r = qq & 511;
                int k = r >> 5, n4 = r & 31;
                *(float4*)&WS3(buf,seg,k,n4*4) = pW[i];
            }
            if (stg){
                XSS(buf,q4*4+0,p_rel)=par.x; XSS(buf,q4*4+1,p_rel)=par.y;
                XSS(buf,q4*4+2,p_rel)=par.z; XSS(buf,q4*4+3,p_rel)=par.w;
                float w0 = lw_s[p_rel*4+0], w1 = lw_s[p_rel*4+1], w2 = lw_s[p_rel*4+2], w3 = lw_s[p_rel*4+3];
                float r0 = rw_s[p_rel*4+0], r1 = rw_s[p_rel*4+1], r2 = rw_s[p_rel*4+2], r3 = rw_s[p_rel*4+3];
                GLX(buf,q4*4+0,p_rel) = w0*ch0.x + w1*ch1.x + w2*ch2.x + w3*ch3.x;
                GLX(buf,q4*4+1,p_rel) = w0*ch0.y + w1*ch1.y + w2*ch2.y + w3*ch3.y;
                GLX(buf,q4*4+2,p_rel) = w0*ch0.z + w1*ch1.z + w2*ch2.z + w3*ch3.z;
                GLX(buf,q4*4+3,p_rel) = w0*ch0.w + w1*ch1.w + w2*ch2.w + w3*ch3.w;
                GRX(buf,q4*4+0,p_rel) = r0*ch0.x + r1*ch1.x + r2*ch2.x + r3*ch3.x;
                GRX(buf,q4*4+1,p_rel) = r0*ch0.y + r1*ch1.y + r2*ch2.y + r3*ch3.y;
                GRX(buf,q4*4+2,p_rel) = r0*ch0.z + r1*ch1.z + r2*ch2.z + r3*ch3.z;
                GRX(buf,q4*4+3,p_rel) = r0*ch0.w + r1*ch1.w + r2*ch2.w + r3*ch3.w;
            }
        };

        u64t acc[4][2];
        #pragma unroll
        for (int r=0;r<4;r++){ acc[r][0]=0; acc[r][1]=0; }

        do_prefetch(0);
        do_commit(0);
        __syncthreads();

        #pragma unroll 1
        for (int c = 0; c < 8; c++){
            int buf = c & 1;
            if (c < 7) do_prefetch((c+1)*16);
            #pragma unroll 4
            for (int k=0;k<16;k++){
                #pragma unroll
                for (int seg=0;seg<3;seg++){
                    const float* As = (seg==0) ? &GLX(buf,k,0) : (seg==1) ? &GRX(buf,k,0) : &XSS(buf,k,0);
                    float4 a = *(const float4*)&As[rgrp*4];
                    ulonglong2 w = *(const ulonglong2*)&WS3(buf,seg,k,tx*4);
                    u64t A0 = pk2(a.x,a.x), A1 = pk2(a.y,a.y), A2 = pk2(a.z,a.z), A3 = pk2(a.w,a.w);
                    acc[0][0] = fma2_(A0, w.x, acc[0][0]);
                    acc[0][1] = fma2_(A0, w.y, acc[0][1]);
                    acc[1][0] = fma2_(A1, w.x, acc[1][0]);
                    acc[1][1] = fma2_(A1, w.y, acc[1][1]);
                    acc[2][0] = fma2_(A2, w.x, acc[2][0]);
                    acc[2][1] = fma2_(A2, w.y, acc[2][1]);
                    acc[3][0] = fma2_(A3, w.x, acc[3][0]);
                    acc[3][1] = fma2_(A3, w.y, acc[3][1]);
                }
            }
            if (c < 7){
                do_commit(buf^1);
                __syncthreads();
            }
        }

        float* fo = featptr(layer);
        float4 bb = *(const float4*)(bconv + layer*HD + tx*4);
        float sqr[4];
        #pragma unroll
        for (int r=0;r<4;r++){
            float v[4];
            upk2(acc[r][0], v[0], v[1]);
            upk2(acc[r][1], v[2], v[3]);
            v[0] = fmaxf(v[0]+bb.x, 0.f); v[1] = fmaxf(v[1]+bb.y, 0.f);
            v[2] = fmaxf(v[2]+bb.z, 0.f); v[3] = fmaxf(v[3]+bb.w, 0.f);
            sqr[r] = v[0]*v[0] + v[1]*v[1] + v[2]*v[2] + v[3]*v[3];
            int loc = l0 + rgrp*4 + r;
            float4 o = {v[0],v[1],v[2],v[3]};
            *(float4*)(fo + (size_t)(g*NPG + loc)*HD + tx*4) = o;
        }
        #pragma unroll
        for (int o=16;o;o>>=1){
            sqr[0] += __shfl_xor_sync(0xffffffffu, sqr[0], o);
            sqr[1] += __shfl_xor_sync(0xffffffffu, sqr[1], o);
            sqr[2] += __shfl_xor_sync(0xffffffffu, sqr[2], o);
            sqr[3] += __shfl_xor_sync(0xffffffffu, sqr[3], o);
        }
        if (tx < 4) atomicAdd(&g_l2[g*NPG + l0 + rgrp*4 + tx], sqr[tx]);
        cluster_sync_fenced();
    }

    // ---- top-8 phase ----
    {
        float* l2s = (float*)smraw;
        float* rv  = (float*)(smraw + 4096);
        int*   ri  = (int*)  (smraw + 4160);
        int*   top8= (int*)  (smraw + 4224);
        for (int i = tid; i < 1024; i += 256) l2s[i] = g_l2[g*1024 + i];
        __syncthreads();
        int warp = tid >> 5;
        for (int t=0;t<8;t++){
            float v = -1e30f; int idx = 1<<30;
            for (int i=tid;i<1024;i+=256){
                float x = l2s[i];
                if (x > v || (x == v && i < idx)){ v = x; idx = i; }
            }
            #pragma unroll
            for (int o=16;o;o>>=1){
                float v2 = __shfl_xor_sync(0xffffffffu, v, o);
                int   i2 = __shfl_xor_sync(0xffffffffu, idx, o);
                if (v2 > v || (v2 == v && i2 < idx)){ v = v2; idx = i2; }
            }
            if (lane == 0){ rv[warp] = v; ri[warp] = idx; }
            __syncthreads();
            if (tid == 0){
                float vv = rv[0]; int ii = ri[0];
                #pragma unroll
                for (int w=1;w<8;w++){
                    if (rv[w] > vv || (rv[w] == vv && ri[w] < ii)){ vv = rv[w]; ii = ri[w]; }
                }
                top8[t] = ii; l2s[ii] = -1e30f;
            }
            __syncthreads();
        }
        int node = top8[y];
        size_t nb = (size_t)(g*NPG + node)*HD;
        for (int i = tid; i < 512; i += 256){
            int dim = i >> 2, c = i & 3;
            float val;
            if (node < NPAR){
                val = (c==0 ? g_f0 : c==1 ? g_f1 : c==2 ? g_f2 : g_f3)[nb + dim];
            } else {
                val = g_h0[nb + dim];
            }
            size_t o = (size_t)(g*1024 + y*128 + dim)*4 + c;
            g_u  [o] = val;
            g_Vc0[o] = val;
        }
    }
    cluster_sync_fenced();

    // ---- VTS phase ----
    {
        ulonglong2* sUp2 = (ulonglong2*)smraw;
        ulonglong2* sVp2 = (ulonglong2*)(smraw + 16384);
        u64t* sMn2 = (u64t*)(smraw + 32768);
        u64t* sZ2  = (u64t*)(smraw + 36864);
        float* sPm = (float*)(smraw + 40960);
        float* sPz = (float*)(smraw + 41984);
        float4* sAcc = (float4*)(smraw + 43008);
        int half = tid >> 7, r = tid & 127;

        for (int i=tid;i<512;i+=256){
            float4 u0 = *(const float4*)&g_u[(size_t)(g*1024 + 2*i  )*4];
            float4 u1 = *(const float4*)&g_u[(size_t)(g*1024 + 2*i+1)*4];
            ulonglong2 A, B;
            A.x = pk2(u0.x,u1.x); A.y = pk2(u0.y,u1.y);
            B.x = pk2(u0.z,u1.z); B.y = pk2(u0.w,u1.w);
            sUp2[2*i] = A; sUp2[2*i+1] = B;
        }
        const int row = y*128 + r;
        float4 u = *(const float4*)&g_u[(size_t)(g*1024 + row)*4];
        u64t U0 = pk2(u.x,u.x), U1 = pk2(u.y,u.y), U2 = pk2(u.z,u.z), U3 = pk2(u.w,u.w);
        const int jlo = half*256, jhi = jlo + 256;

        #pragma unroll 1
        for (int it = 0; it < 3; it++){
            const float* vin  = (it==2) ? g_Vc1 : g_Vc0;
            float*       vout = (it==1) ? g_Vc1 : g_Vc0;
            for (int p=tid;p<512;p+=256){
                size_t iA = (size_t)(g*1024 + 2*p)*4;
                float4 a = *(const float4*)&vin[iA];
                float4 b = *(const float4*)&vin[iA+4];
                if (it){
                    float4 p0 = *(const float4*)&g_aP[iA];
                    float4 q0 = *(const float4*)&g_aP[iA+4];
                    a.x += p0.x; a.y += p0.y; a.z += p0.z; a.w += p0.w;
                    b.x += q0.x; b.y += q0.y; b.z += q0.z; b.w += q0.w;
                    if (p >= y*64 && p < y*64 + 64){
                        *(float4*)&vout[iA]   = a;
                        *(float4*)&vout[iA+4] = b;
                    }
                }
                ulonglong2 A, B;
                A.x = pk2(a.x,b.x); A.y = pk2(a.y,b.y);
                B.x = pk2(a.z,b.z); B.y = pk2(a.w,b.w);
                sVp2[2*p] = A; sVp2[2*p+1] = B;
            }
            __syncthreads();
            {
                float ma = -1e30f, mb = -1e30f;
                #pragma unroll 2
                for (int jp=jlo;jp<jhi;jp+=2){
                    ulonglong2 P01 = sVp2[jp*2],   P23 = sVp2[jp*2+1];
                    ulonglong2 Q01 = sVp2[jp*2+2], Q23 = sVp2[jp*2+3];
                    u64t t = mul2_(U0, P01.x); u64t s = mul2_(U0, Q01.x);
                    t = fma2_(U1, P01.y, t);   s = fma2_(U1, Q01.y, s);
                    t = fma2_(U2, P23.x, t);   s = fma2_(U2, Q23.x, s);
                    t = fma2_(U3, P23.y, t);   s = fma2_(U3, Q23.y, s);
                    float t0,t1,s0,s1; upk2(t,t0,t1); upk2(s,s0,s1);
                    ma = fmaxf(ma, fmaxf(t0,t1));
                    mb = fmaxf(mb, fmaxf(s0,s1));
                }
                float m = fmaxf(ma, mb);
                u64t MN = pk2(-m, -m);
                float za = 0.f, zb = 0.f;
                #pragma unroll 2
                for (int jp=jlo;jp<jhi;jp+=2){
                    ulonglong2 P01 = sVp2[jp*2],   P23 = sVp2[jp*2+1];
                    ulonglong2 Q01 = sVp2[jp*2+2], Q23 = sVp2[jp*2+3];
                    u64t t = mul2_(U0, P01.x); u64t s = mul2_(U0, Q01.x);
                    t = fma2_(U1, P01.y, t);   s = fma2_(U1, Q01.y, s);
                    t = fma2_(U2, P23.x, t);   s = fma2_(U2, Q23.x, s);
                    t = fma2_(U3, P23.y, t);   s = fma2_(U3, Q23.y, s);
                    t = add2_(t, MN);          s = add2_(s, MN);
                    float t0,t1,s0,s1; upk2(t,t0,t1); upk2(s,s0,s1);
                    za += __expf(t0); za += __expf(t1);
                    zb += __expf(s0); zb += __expf(s1);
                }
                sPm[half*128 + r] = m;
                sPz[half*128 + r] = za + zb;
            }
            __syncthreads();
            if (half == 0){
                float m0 = sPm[r], m1 = sPm[128 + r];
                float M = fmaxf(m0, m1);
                float Z = sPz[r]*__expf(m0 - M) + sPz[128 + r]*__expf(m1 - M);
                g_pM[g*1024 + row] = M;
                g_pZ[g*1024 + row] = Z;
            }
            cluster_sync_fenced();
            for (int p=tid;p<512;p+=256){
                float m0 = g_pM[g*1024 + 2*p], m1 = g_pM[g*1024 + 2*p+1];
                float Z0 = g_pZ[g*1024 + 2*p], Z1 = g_pZ[g*1024 + 2*p+1];
                sMn2[p] = pk2(-m0, -m1);
                sZ2 [p] = pk2(1.f/Z0, 1.f/Z1);
            }
            __syncthreads();
            {
                const float* vread = (it==1) ? g_Vc1 : g_Vc0;
                float4 c = *(const float4*)&vread[(size_t)(g*1024 + row)*4];
                u64t C0 = pk2(c.x,c.x), C1 = pk2(c.y,c.y), C2 = pk2(c.z,c.z), C3 = pk2(c.w,c.w);
                u64t aXa=0,aYa=0,aZa=0,aWa=0, aXb=0,aYb=0,aZb=0,aWb=0;
                #pragma unroll 2
                for (int ip=jlo;ip<jhi;ip+=2){
                    ulonglong2 P01 = sUp2[ip*2],   P23 = sUp2[ip*2+1];
                    ulonglong2 Q01 = sUp2[ip*2+2], Q23 = sUp2[ip*2+3];
                    u64t t = mul2_(C0, P01.x);  u64t s2 = mul2_(C0, Q01.x);
                    t = fma2_(C1, P01.y, t);    s2 = fma2_(C1, Q01.y, s2);
                    t = fma2_(C2, P23.x, t);    s2 = fma2_(C2, Q23.x, s2);
                    t = fma2_(C3, P23.y, t);    s2 = fma2_(C3, Q23.y, s2);
                    t = add2_(t, sMn2[ip]);     s2 = add2_(s2, sMn2[ip+1]);
                    float t0,t1,s0,s1; upk2(t,t0,t1); upk2(s2,s0,s1);
                    u64t wza = mul2_(pk2(__expf(t0), __expf(t1)), sZ2[ip]);
                    u64t wzb = mul2_(pk2(__expf(s0), __expf(s1)), sZ2[ip+1]);
                    aXa = fma2_(wza, P01.x, aXa);
                    aYa = fma2_(wza, P01.y, aYa);
                    aZa = fma2_(wza, P23.x, aZa);
                    aWa = fma2_(wza, P23.y, aWa);
                    aXb = fma2_(wzb, Q01.x, aXb);
                    aYb = fma2_(wzb, Q01.y, aYb);
                    aZb = fma2_(wzb, Q23.x, aZb);
                    aWb = fma2_(wzb, Q23.y, aWb);
                }
                float x0,x1,y0,y1,z0,z1,w0,w1;
                upk2(add2_(aXa,aXb), x0, x1);
                upk2(add2_(aYa,aYb), y0, y1);
                upk2(add2_(aZa,aZb), z0, z1);
                upk2(add2_(aWa,aWb), w0, w1);
                float a0 = x0+x1, a1 = y0+y1, a2 = z0+z1, a3 = w0+w1;
                if (half == 1){
                    float4 h1 = {a0, a1, a2, a3};
                    sAcc[r] = h1;
                }
                __syncthreads();
                if (half == 0){
                    float4 h1 = sAcc[r];
                    a0 += h1.x; a1 += h1.y; a2 += h1.z; a3 += h1.w;
                    if (it < 2){
                        float4 o = {a0, a1, a2, a3};
                        *(float4*)&g_aP[(size_t)(g*1024 + row)*4] = o;
                    } else {
                        float sq = a0*a0 + a1*a1 + a2*a2 + a3*a3;
                        float sc = sq/(1.f+sq)/(sqrtf(sq + 1e-10f) + 1e-8f);
                        float4 o = {a0*sc, a1*sc, a2*sc, a3*sc};
                        *(float4*)&g_SC[(size_t)(g*1024 + row)*4] = o;
                    }
                }
            }
            if (it < 2) cluster_sync_fenced();
        }
    }
}

// ---------------- zsum: zs[r][b][s][c] += ... (coalesced atomics) ----------------
__global__ __launch_bounds__(512) void k_zsum2(const float* __restrict__ Wjm, int round0, int r){
    __shared__ __align__(16) float4 Ws4[64*16];
    __shared__ __align__(16) float4 Xs4[64*32];
    int s = blockIdx.x;
    int n0 = blockIdx.y*64;
    int tid = threadIdx.x;
    const float4* W4 = (const float4*)Wjm;
    #pragma unroll
    for (int i = tid; i < 1024; i += 512){
        int n = i >> 4, c = i & 15;
        Ws4[i] = W4[(size_t)(n0+n)*800 + c*50 + s];
    }
    #pragma unroll
    for (int i = tid; i < 2048; i += 512){
        int n = i >> 5, b = i & 31;
        float ga = round0 ? 0.02f : g_gamma[(size_t)(b*1024 + n0 + n)*50 + s];
        float4 sc = *(const float4*)&g_SC[(size_t)(b*1024 + n0 + n)*4];
        float4 x; x.x = ga*sc.x; x.y = ga*sc.y; x.z = ga*sc.z; x.w = ga*sc.w;
        Xs4[n*32 + b] = x;
    }
    __syncthreads();
    int c = tid & 15, b = tid >> 4;
    float acc = 0.f;
    #pragma unroll 8
    for (int n = 0; n < 64; n++){
        float4 w = Ws4[n*16 + c];
        float4 x = Xs4[n*32 + b];
        acc += w.x*x.x + w.y*x.y + w.z*x.z + w.w*x.w;
    }
    atomicAdd(&g_zs[r*NG*CS + b*CS + s*DCCN + c], acc);
}

// ---------------- z[b][s][c] = squash_c(zs[r][b][s][:]) ----------------
__global__ void k_zfin(int r){
    int b = blockIdx.x, s = threadIdx.x;
    if (s >= NCLS) return;
    const float* zsp = g_zs + r*NG*CS + b*CS + s*DCCN;
    float4 v0 = *(const float4*)(zsp + 0);
    float4 v1 = *(const float4*)(zsp + 4);
    float4 v2 = *(const float4*)(zsp + 8);
    float4 v3 = *(const float4*)(zsp + 12);
    float sq = v0.x*v0.x+v0.y*v0.y+v0.z*v0.z+v0.w*v0.w
             + v1.x*v1.x+v1.y*v1.y+v1.z*v1.z+v1.w*v1.w
             + v2.x*v2.x+v2.y*v2.y+v2.z*v2.z+v2.w*v2.w
             + v3.x*v3.x+v3.y*v3.y+v3.z*v3.z+v3.w*v3.w;
    float sc = sq/(1.f+sq)/(sqrtf(sq + 1e-10f) + 1e-8f);
    float* zp = g_z + b*CS + s*DCCN;
    float4 o0 = {v0.x*sc,v0.y*sc,v0.z*sc,v0.w*sc};
    float4 o1 = {v1.x*sc,v1.y*sc,v1.z*sc,v1.w*sc};
    float4 o2 = {v2.x*sc,v2.y*sc,v2.z*sc,v2.w*sc};
    float4 o3 = {v3.x*sc,v3.y*sc,v3.z*sc,v3.w*sc};
    *(float4*)(zp + 0) = o0;
    *(float4*)(zp + 4) = o1;
    *(float4*)(zp + 8) = o2;
    *(float4*)(zp + 12) = o3;
}

// ---------------- fused delta + gamma (vectorized z loads) ----------------
__global__ __launch_bounds__(512) void k_dg(const float* __restrict__ Wjm, int accum){
    __shared__ __align__(16) float4 Ws4[800];
    __shared__ float sdel[1600];
    __shared__ float smx[32], siz[32];
    int n = blockIdx.x;
    int tid = threadIdx.x;
    const float4* W4 = (const float4*)Wjm + (size_t)n*800;
    for (int i = tid; i < 800; i += 512) Ws4[i] = W4[i];
    __syncthreads();
    for (int p = tid; p < 1600; p += 512){
        int b = p / 50, s = p % 50;
        const float* zp = g_z + b*CS + s*DCCN;   // contiguous 16
        float4 z0 = *(const float4*)(zp + 0);
        float4 z1 = *(const float4*)(zp + 4);
        float4 z2 = *(const float4*)(zp + 8);
        float4 z3 = *(const float4*)(zp + 12);
        float zz[16] = {z0.x,z0.y,z0.z,z0.w, z1.x,z1.y,z1.z,z1.w,
                        z2.x,z2.y,z2.z,z2.w, z3.x,z3.y,z3.z,z3.w};
        float tx=0.f, ty=0.f, tz=0.f, tw=0.f;
        #pragma unroll
        for (int c = 0; c < 16; c++){
            float4 w = Ws4[c*50 + s];
            tx += w.x*zz[c]; ty += w.y*zz[c]; tz += w.z*zz[c]; tw += w.w*zz[c];
        }
        float4 sc = *(const float4*)&g_SC[(size_t)(b*1024 + n)*4];
        float d = tx*sc.x + ty*sc.y + tz*sc.z + tw*sc.w;
        size_t o = (size_t)(b*1024 + n)*50 + s;
        if (accum) d += g_delta[o];
        g_delta[o] = d;
        sdel[p] = d;
    }
    __syncthreads();
    if (tid < 32){
        float m = -1e30f;
        for (int k=0;k<NCLS;k++) m = fmaxf(m, sdel[tid*50 + k]);
        float Z = 0.f;
        for (int k=0;k<NCLS;k++) Z += __expf(sdel[tid*50 + k] - m);
        smx[tid] = m; siz[tid] = 1.f/Z;
    }
    __syncthreads();
    for (int p = tid; p < 1600; p += 512){
        int b = p / 50;
        size_t o = (size_t)(b*1024 + n)*50 + (p % 50);
        g_gamma[o] = __expf(sdel[p] - smx[b]) * siz[b];
    }
}

// ---------------- final: z = squash(zs[2]) and logits ----------------
__global__ void k_zlogit(float* __restrict__ out){
    int b = blockIdx.x, s = threadIdx.x;
    if (s >= NCLS) return;
    const float* zsp = g_zs + 2*NG*CS + b*CS + s*DCCN;
    float4 v0 = *(const float4*)(zsp + 0);
    float4 v1 = *(const float4*)(zsp + 4);
    float4 v2 = *(const float4*)(zsp + 8);
    float4 v3 = *(const float4*)(zsp + 12);
    float sq = v0.x*v0.x+v0.y*v0.y+v0.z*v0.z+v0.w*v0.w
             + v1.x*v1.x+v1.y*v1.y+v1.z*v1.z+v1.w*v1.w
             + v2.x*v2.x+v2.y*v2.y+v2.z*v2.z+v2.w*v2.w
             + v3.x*v3.x+v3.y*v3.y+v3.z*v3.z+v3.w*v3.w;
    float sc = sq/(1.f+sq)/(sqrtf(sq + 1e-10f) + 1e-8f);
    float sq2 = sq*sc*sc;
    float lg = sqrtf(sq2 + 1e-10f);
    out[b*NCLS + s] = lg;
    out[NG*NCLS + b*NCLS + s] = lg;
}

// ---------------- launch ----------------
extern "C" void kernel_launch(void* const* d_in, const int* in_sizes, int n_in,
                              void* d_out, int out_size){
    const int*   type_ids  = (const int*)  d_in[0];
    const int*   token_ids = (const int*)  d_in[1];
    const float* lw        = (const float*)d_in[4];
    const float* rw        = (const float*)d_in[5];
    const float* temb      = (const float*)d_in[7];
    const float* kemb      = (const float*)d_in[8];
    const float* WL        = (const float*)d_in[9];
    const float* WR        = (const float*)d_in[10];
    const float* WT        = (const float*)d_in[11];
    const float* bconv     = (const float*)d_in[12];
    const float* Wjm       = (const float*)d_in[13];
    float* out = (float*)d_out;

    k_mega<<<dim3(NG,8,1), 256>>>(type_ids, token_ids, temb, kemb,
                                  WL, WR, WT, bconv, lw, rw);
    // round 0 (gamma uniform = 1/50)
    k_zsum2<<<dim3(NCLS,16), 512>>>(Wjm, 1, 0);
    k_zfin<<<NG, 64>>>(0);
    k_dg<<<NPG, 512>>>(Wjm, 0);
    // round 1
    k_zsum2<<<dim3(NCLS,16), 512>>>(Wjm, 0, 1);
    k_zfin<<<NG, 64>>>(1);
    k_dg<<<NPG, 512>>>(Wjm, 1);
    // round 2 (final)
    k_zsum2<<<dim3(NCLS,16), 512>>>(Wjm, 0, 2);
    k_zlogit<<<NG, 64>>>(out);
}

// round 16
// speedup vs baseline: 1.0332x; 1.0332x over previous
#include <cuda_runtime.h>
#include <cuda_bf16.h>
#include <cstdint>

#define NG   32
#define NPG  1024
#define NN   (NG*NPG)
#define HD   128
#define NLAY 4
#define NPAR 256
#define NPT  (NG*NPAR)
#define NCLS 50
#define DCCN 16
#define CS   (DCCN*NCLS)   // 800

typedef unsigned long long u64t;

__device__ __forceinline__ u64t pk2(float x, float y){ u64t r; asm("mov.b64 %0, {%1,%2};" : "=l"(r) : "f"(x), "f"(y)); return r; }
__device__ __forceinline__ void upk2(u64t p, float& x, float& y){ asm("mov.b64 {%0,%1}, %2;" : "=f"(x), "=f"(y) : "l"(p)); }
__device__ __forceinline__ u64t fma2_(u64t a, u64t b, u64t c){ u64t d; asm("fma.rn.f32x2 %0, %1, %2, %3;" : "=l"(d) : "l"(a), "l"(b), "l"(c)); return d; }
__device__ __forceinline__ u64t mul2_(u64t a, u64t b){ u64t d; asm("mul.rn.f32x2 %0, %1, %2;" : "=l"(d) : "l"(a), "l"(b)); return d; }
__device__ __forceinline__ u64t add2_(u64t a, u64t b){ u64t d; asm("add.rn.f32x2 %0, %1, %2;" : "=l"(d) : "l"(a), "l"(b)); return d; }

__device__ __forceinline__ void cluster_sync_fenced(){
    __threadfence();
    asm volatile("barrier.cluster.arrive.aligned;" ::: "memory");
    asm volatile("barrier.cluster.wait.aligned;" ::: "memory");
}

// ---------------- device scratch ----------------
__device__ __align__(256) float g_h0[NN*HD];
__device__ __align__(256) float g_f0[NN*HD];
__device__ __align__(256) float g_f1[NN*HD];
__device__ __align__(256) float g_f2[NN*HD];
__device__ __align__(256) float g_f3[NN*HD];
__device__ __align__(256) float g_l2[NN];
__device__ __align__(256) float g_u  [NN*4];
__device__ __align__(256) float g_Vc0[NN*4];
__device__ __align__(256) float g_Vc1[NN*4];
__device__ __align__(256) float g_pM [NN];
__device__ __align__(256) float g_pZ [NN];
__device__ __align__(256) float g_aP [NN*4];
__device__ __align__(256) float g_SC [NN*4];
__device__ __align__(256) float g_delta[NN*NCLS];
__device__ __align__(256) float g_gamma[NN*NCLS];
__device__ __align__(256) float g_zs[3*NG*CS];   // [r][b][c*50+s]
__device__ __align__(256) float g_z [NG*CS];

__device__ __forceinline__ float* featptr(int l){
    switch(l){ case 0: return g_f0; case 1: return g_f1; case 2: return g_f2; default: return g_f3; }
}

// ---------------- embedding + leaf l2 ----------------
__global__ void k_embed(const int* __restrict__ type_ids, const int* __restrict__ token_ids,
                        const float* __restrict__ temb, const float* __restrict__ kemb){
    int idx = blockIdx.x*256 + threadIdx.x;
    int n = idx >> 5, q = idx & 31;
    float4 v;
    if (q < 16) v = *(const float4*)(temb + (size_t)type_ids[n]*64 + q*4);
    else        v = *(const float4*)(kemb + (size_t)token_ids[n]*64 + (q-16)*4);
    size_t o = (size_t)n*HD + q*4;
    *(float4*)(g_h0 + o) = v;
    bool leaf = (n & (NPG-1)) >= NPAR;
    float sq = v.x*v.x + v.y*v.y + v.z*v.z + v.w*v.w;
    #pragma unroll
    for (int s=16;s;s>>=1) sq += __shfl_xor_sync(0xffffffffu, sq, s);
    if (q == 0) g_l2[n] = leaf ? 4.f*sq : 0.f;
}

// ---------------- fused gather + GEMM, double-buffered pipeline (frozen R11) ----------------
__global__ __launch_bounds__(256) void k_gemm(const float* __restrict__ WLp,
        const float* __restrict__ WRp, const float* __restrict__ WTp,
        const float* __restrict__ bconv,
        const float* __restrict__ lw, const float* __restrict__ rw, int layer){
    __shared__ __align__(16) float GLx[2][16][36];
    __shared__ __align__(16) float GRx[2][16][36];
    __shared__ __align__(16) float Xs [2][16][36];
    __shared__ __align__(16) float Ws3[2][3][16][128];
    __shared__ float lw_s[128], rw_s[128];
    const int tid = threadIdx.x;
    const int row0 = blockIdx.x*32;
    const int g = row0 >> 8, l0 = row0 & 255;
    const float* hin = (layer==0) ? g_h0 : featptr(layer-1);
    const float* Wb[3] = { WLp + layer*HD*HD, WRp + layer*HD*HD, WTp + layer*HD*HD };
    const int rgrp = tid >> 5;
    const int tx   = tid & 31;
    const int p_rel = tid >> 2, q = tid & 3;
    const bool stg = tid < 128;

    if (stg){
        int e_local = 4*l0 + tid;
        bool valid = e_local < 1023;
        lw_s[tid] = valid ? lw[g*1023 + e_local] : 0.f;
        rw_s[tid] = valid ? rw[g*1023 + e_local] : 0.f;
    }
    __syncthreads();

    int cloc[4];
    #pragma unroll
    for (int j=0;j<4;j++){
        int c_local = 4*(l0+p_rel) + 1 + j;
        if (c_local > 1023) c_local = 1023;
        cloc[j] = c_local;
    }

    float4 pW[6];
    float4 par, ch0, ch1, ch2, ch3;

    auto do_prefetch = [&](int k0){
        #pragma unroll
        for (int i=0;i<6;i++){
            int qq = tid + i*256;
            int seg = qq >> 9, r = qq & 511;
            int k = r >> 5, n4 = r & 31;
            pW[i] = *(const float4*)(Wb[seg] + (size_t)(k0+k)*HD + n4*4);
        }
        if (stg){
            par = *(const float4*)(hin + (size_t)(g*NPG + l0 + p_rel)*HD + k0 + q*4);
            const float* c0s = (cloc[0] < NPAR) ? hin : g_h0;
            const float* c1s = (cloc[1] < NPAR) ? hin : g_h0;
            const float* c2s = (cloc[2] < NPAR) ? hin : g_h0;
            const float* c3s = (cloc[3] < NPAR) ? hin : g_h0;
            ch0 = *(const float4*)(c0s + (size_t)(g*NPG + cloc[0])*HD + k0 + q*4);
            ch1 = *(const float4*)(c1s + (size_t)(g*NPG + cloc[1])*HD + k0 + q*4);
            ch2 = *(const float4*)(c2s + (size_t)(g*NPG + cloc[2])*HD + k0 + q*4);
            ch3 = *(const float4*)(c3s + (size_t)(g*NPG + cloc[3])*HD + k0 + q*4);
        }
    };
    auto do_commit = [&](int buf){
        #pragma unroll
        for (int i=0;i<6;i++){
            int qq = tid + i*256;
            int seg = qq >> 9, r = qq & 511;
            int k = r >> 5, n4 = r & 31;
            *(float4*)&Ws3[buf][seg][k][n4*4] = pW[i];
        }
        if (stg){
            Xs[buf][q*4+0][p_rel]=par.x; Xs[buf][q*4+1][p_rel]=par.y;
            Xs[buf][q*4+2][p_rel]=par.z; Xs[buf][q*4+3][p_rel]=par.w;
            float w0 = lw_s[p_rel*4+0], w1 = lw_s[p_rel*4+1], w2 = lw_s[p_rel*4+2], w3 = lw_s[p_rel*4+3];
            float r0 = rw_s[p_rel*4+0], r1 = rw_s[p_rel*4+1], r2 = rw_s[p_rel*4+2], r3 = rw_s[p_rel*4+3];
            GLx[buf][q*4+0][p_rel] = w0*ch0.x + w1*ch1.x + w2*ch2.x + w3*ch3.x;
            GLx[buf][q*4+1][p_rel] = w0*ch0.y + w1*ch1.y + w2*ch2.y + w3*ch3.y;
            GLx[buf][q*4+2][p_rel] = w0*ch0.z + w1*ch1.z + w2*ch2.z + w3*ch3.z;
            GLx[buf][q*4+3][p_rel] = w0*ch0.w + w1*ch1.w + w2*ch2.w + w3*ch3.w;
            GRx[buf][q*4+0][p_rel] = r0*ch0.x + r1*ch1.x + r2*ch2.x + r3*ch3.x;
            GRx[buf][q*4+1][p_rel] = r0*ch0.y + r1*ch1.y + r2*ch2.y + r3*ch3.y;
            GRx[buf][q*4+2][p_rel] = r0*ch0.z + r1*ch1.z + r2*ch2.z + r3*ch3.z;
            GRx[buf][q*4+3][p_rel] = r0*ch0.w + r1*ch1.w + r2*ch2.w + r3*ch3.w;
        }
    };

    u64t acc[4][2];
    #pragma unroll
    for (int r=0;r<4;r++){ acc[r][0]=0; acc[r][1]=0; }

    do_prefetch(0);
    do_commit(0);
    __syncthreads();

    #pragma unroll 1
    for (int c = 0; c < 8; c++){
        int buf = c & 1;
        if (c < 7) do_prefetch((c+1)*16);
        #pragma unroll 4
        for (int k=0;k<16;k++){
            #pragma unroll
            for (int seg=0;seg<3;seg++){
                const float* As = (seg==0) ? &GLx[buf][k][0] : (seg==1) ? &GRx[buf][k][0] : &Xs[buf][k][0];
                float4 a = *(const float4*)&As[rgrp*4];
                ulonglong2 w = *(const ulonglong2*)&Ws3[buf][seg][k][tx*4];
                u64t A0 = pk2(a.x,a.x), A1 = pk2(a.y,a.y), A2 = pk2(a.z,a.z), A3 = pk2(a.w,a.w);
                acc[0][0] = fma2_(A0, w.x, acc[0][0]);
                acc[0][1] = fma2_(A0, w.y, acc[0][1]);
                acc[1][0] = fma2_(A1, w.x, acc[1][0]);
                acc[1][1] = fma2_(A1, w.y, acc[1][1]);
                acc[2][0] = fma2_(A2, w.x, acc[2][0]);
                acc[2][1] = fma2_(A2, w.y, acc[2][1]);
                acc[3][0] = fma2_(A3, w.x, acc[3][0]);
                acc[3][1] = fma2_(A3, w.y, acc[3][1]);
            }
        }
        if (c < 7){
            do_commit(buf^1);
            __syncthreads();
        }
    }

    float* fo = featptr(layer);
    float4 bb = *(const float4*)(bconv + layer*HD + tx*4);
    float sqr[4];
    #pragma unroll
    for (int r=0;r<4;r++){
        float v[4];
        upk2(acc[r][0], v[0], v[1]);
        upk2(acc[r][1], v[2], v[3]);
        v[0] = fmaxf(v[0]+bb.x, 0.f); v[1] = fmaxf(v[1]+bb.y, 0.f);
        v[2] = fmaxf(v[2]+bb.z, 0.f); v[3] = fmaxf(v[3]+bb.w, 0.f);
        sqr[r] = v[0]*v[0] + v[1]*v[1] + v[2]*v[2] + v[3]*v[3];
        int loc = l0 + rgrp*4 + r;
        float4 o = {v[0],v[1],v[2],v[3]};
        *(float4*)(fo + (size_t)(g*NPG + loc)*HD + tx*4) = o;
    }
    #pragma unroll
    for (int o=16;o;o>>=1){
        sqr[0] += __shfl_xor_sync(0xffffffffu, sqr[0], o);
        sqr[1] += __shfl_xor_sync(0xffffffffu, sqr[1], o);
        sqr[2] += __shfl_xor_sync(0xffffffffu, sqr[2], o);
        sqr[3] += __shfl_xor_sync(0xffffffffu, sqr[3], o);
    }
    if (tx < 4) atomicAdd(&g_l2[g*NPG + l0 + rgrp*4 + tx], sqr[tx]);
}

// ---------------- top-8 per graph + gather u, init Vc0; zero zs ----------------
__global__ __launch_bounds__(1024) void k_top(){
    __shared__ float l2s[1024];
    __shared__ float rv[32]; __shared__ int ri[32];
    __shared__ int top8[8];
    int g = blockIdx.x, tid = threadIdx.x;
    int lane = tid & 31, warp = tid >> 5;
    for (int i = g*1024 + tid; i < 3*NG*CS; i += NG*1024) g_zs[i] = 0.f;
    l2s[tid] = g_l2[g*1024 + tid];
    __syncthreads();
    for (int t=0;t<8;t++){
        float v = l2s[tid]; int idx = tid;
        #pragma unroll
        for (int o=16;o;o>>=1){
            float v2 = __shfl_xor_sync(0xffffffffu, v, o);
            int   i2 = __shfl_xor_sync(0xffffffffu, idx, o);
            if (v2 > v || (v2 == v && i2 < idx)){ v = v2; idx = i2; }
        }
        if (lane == 0){ rv[warp] = v; ri[warp] = idx; }
        __syncthreads();
        if (warp == 0){
            float vv = rv[lane]; int ii = ri[lane];
            #pragma unroll
            for (int o=16;o;o>>=1){
                float v2 = __shfl_xor_sync(0xffffffffu, vv, o);
                int   i2 = __shfl_xor_sync(0xffffffffu, ii, o);
                if (v2 > vv || (v2 == vv && i2 < ii)){ vv = v2; ii = i2; }
            }
            if (lane == 0){ top8[t] = ii; l2s[ii] = -1e30f; }
        }
        __syncthreads();
    }
    int bcap = tid >> 7, hh = tid & 127;
    int node = top8[bcap];
    size_t nb = (size_t)(g*NPG + node)*HD + hh;
    float4 uv;
    if (node < NPAR){
        uv.x = g_f0[nb]; uv.y = g_f1[nb]; uv.z = g_f2[nb]; uv.w = g_f3[nb];
    } else {
        float h = g_h0[nb];
        uv.x = h; uv.y = h; uv.z = h; uv.w = h;
    }
    *(float4*)&g_u  [(size_t)(g*1024 + tid)*4] = uv;
    *(float4*)&g_Vc0[(size_t)(g*1024 + tid)*4] = uv;
}

// ---------------- fused VTS: 3 iterations, 8-CTA clusters, ONLINE-softmax phA ----------
__global__ __launch_bounds__(128) __cluster_dims__(1,8,1) void k_vts(){
    __shared__ __align__(16) ulonglong2 sUp2[1024];
    __shared__ __align__(16) ulonglong2 sVp2[1024];
    __shared__ u64t sMn2[512];
    __shared__ u64t sZ2 [512];
    int g = blockIdx.x, y = blockIdx.y, tid = threadIdx.x;

    for (int i=tid;i<512;i+=128){
        float4 u0 = *(const float4*)&g_u[(size_t)(g*1024 + 2*i  )*4];
        float4 u1 = *(const float4*)&g_u[(size_t)(g*1024 + 2*i+1)*4];
        ulonglong2 A, B;
        A.x = pk2(u0.x,u1.x); A.y = pk2(u0.y,u1.y);
        B.x = pk2(u0.z,u1.z); B.y = pk2(u0.w,u1.w);
        sUp2[2*i] = A; sUp2[2*i+1] = B;
    }
    const int row = y*128 + tid;
    float4 u = *(const float4*)&g_u[(size_t)(g*1024 + row)*4];
    u64t U0 = pk2(u.x,u.x), U1 = pk2(u.y,u.y), U2 = pk2(u.z,u.z), U3 = pk2(u.w,u.w);

    #pragma unroll 1
    for (int it = 0; it < 3; it++){
        const float* vin  = (it==2) ? g_Vc1 : g_Vc0;
        float*       vout = (it==1) ? g_Vc1 : g_Vc0;
        // ---- staging: all 1024 cols, fold aP, write own cols ----
        for (int p=tid;p<512;p+=128){
            size_t iA = (size_t)(g*1024 + 2*p)*4;
            float4 a = *(const float4*)&vin[iA];
            float4 b = *(const float4*)&vin[iA+4];
            if (it){
                float4 p0 = *(const float4*)&g_aP[iA];
                float4 q0 = *(const float4*)&g_aP[iA+4];
                a.x += p0.x; a.y += p0.y; a.z += p0.z; a.w += p0.w;
                b.x += q0.x; b.y += q0.y; b.z += q0.z; b.w += q0.w;
                if (p >= y*64 && p < y*64 + 64){
                    *(float4*)&vout[iA]   = a;
                    *(float4*)&vout[iA+4] = b;
                }
            }
            ulonglong2 A, B;
            A.x = pk2(a.x,b.x); A.y = pk2(a.y,b.y);
            B.x = pk2(a.z,b.z); B.y = pk2(a.w,b.w);
            sVp2[2*p] = A; sVp2[2*p+1] = B;
        }
        __syncthreads();
        // ---- phA: ONE pass, online max+sumexp, 2 streams ----
        {
            float ma = -1e30f, za = 0.f, mb = -1e30f, zb = 0.f;
            #pragma unroll 2
            for (int jp=0;jp<512;jp+=2){
                ulonglong2 P01 = sVp2[jp*2],   P23 = sVp2[jp*2+1];
                ulonglong2 Q01 = sVp2[jp*2+2], Q23 = sVp2[jp*2+3];
                u64t t = mul2_(U0, P01.x); u64t s = mul2_(U0, Q01.x);
                t = fma2_(U1, P01.y, t);   s = fma2_(U1, Q01.y, s);
                t = fma2_(U2, P23.x, t);   s = fma2_(U2, Q23.x, s);
                t = fma2_(U3, P23.y, t);   s = fma2_(U3, Q23.y, s);
                float t0,t1,s0,s1; upk2(t,t0,t1); upk2(s,s0,s1);
                float mxa = fmaxf(t0,t1);
                if (mxa > ma){ za *= __expf(ma - mxa); ma = mxa; }
                za += __expf(t0 - ma) + __expf(t1 - ma);
                float mxb = fmaxf(s0,s1);
                if (mxb > mb){ zb *= __expf(mb - mxb); mb = mxb; }
                zb += __expf(s0 - mb) + __expf(s1 - mb);
            }
            float M = fmaxf(ma, mb);
            float Z = za*__expf(ma - M) + zb*__expf(mb - M);
            g_pM[g*1024 + row] = M;
            g_pZ[g*1024 + row] = Z;
        }
        cluster_sync_fenced();
        // ---- phB staging ----
        for (int p=tid;p<512;p+=128){
            float m0 = g_pM[g*1024 + 2*p], m1 = g_pM[g*1024 + 2*p+1];
            float Z0 = g_pZ[g*1024 + 2*p], Z1 = g_pZ[g*1024 + 2*p+1];
            sMn2[p] = pk2(-m0, -m1);
            sZ2 [p] = pk2(1.f/Z0, 1.f/Z1);
        }
        __syncthreads();
        // ---- phB: transposed-pair accumulation ----
        {
            const float* vread = (it==1) ? g_Vc1 : g_Vc0;
            float4 c = *(const float4*)&vread[(size_t)(g*1024 + row)*4];
            u64t C0 = pk2(c.x,c.x), C1 = pk2(c.y,c.y), C2 = pk2(c.z,c.z), C3 = pk2(c.w,c.w);
            u64t aXa=0,aYa=0,aZa=0,aWa=0, aXb=0,aYb=0,aZb=0,aWb=0;
            #pragma unroll 2
            for (int ip=0;ip<512;ip+=2){
                ulonglong2 P01 = sUp2[ip*2],   P23 = sUp2[ip*2+1];
                ulonglong2 Q01 = sUp2[ip*2+2], Q23 = sUp2[ip*2+3];
                u64t t = mul2_(C0, P01.x);  u64t s2 = mul2_(C0, Q01.x);
                t = fma2_(C1, P01.y, t);    s2 = fma2_(C1, Q01.y, s2);
                t = fma2_(C2, P23.x, t);    s2 = fma2_(C2, Q23.x, s2);
                t = fma2_(C3, P23.y, t);    s2 = fma2_(C3, Q23.y, s2);
                t = add2_(t, sMn2[ip]);     s2 = add2_(s2, sMn2[ip+1]);
                float t0,t1,s0,s1; upk2(t,t0,t1); upk2(s2,s0,s1);
                u64t wza = mul2_(pk2(__expf(t0), __expf(t1)), sZ2[ip]);
                u64t wzb = mul2_(pk2(__expf(s0), __expf(s1)), sZ2[ip+1]);
                aXa = fma2_(wza, P01.x, aXa);
                aYa = fma2_(wza, P01.y, aYa);
                aZa = fma2_(wza, P23.x, aZa);
                aWa = fma2_(wza, P23.y, aWa);
                aXb = fma2_(wzb, Q01.x, aXb);
                aYb = fma2_(wzb, Q01.y, aYb);
                aZb = fma2_(wzb, Q23.x, aZb);
                aWb = fma2_(wzb, Q23.y, aWb);
            }
            float x0,x1,y0,y1,z0,z1,w0,w1;
            upk2(add2_(aXa,aXb), x0, x1);
            upk2(add2_(aYa,aYb), y0, y1);
            upk2(add2_(aZa,aZb), z0, z1);
            upk2(add2_(aWa,aWb), w0, w1);
            float a0 = x0+x1, a1 = y0+y1, a2 = z0+z1, a3 = w0+w1;
            if (it < 2){
                float4 o = {a0, a1, a2, a3};
                *(float4*)&g_aP[(size_t)(g*1024 + row)*4] = o;
            } else {
                float sq = a0*a0 + a1*a1 + a2*a2 + a3*a3;
                float sc = sq/(1.f+sq)/(sqrtf(sq + 1e-10f) + 1e-8f);
                float4 o = {a0*sc, a1*sc, a2*sc, a3*sc};
                *(float4*)&g_SC[(size_t)(g*1024 + row)*4] = o;
            }
        }
        if (it < 2) cluster_sync_fenced();
    }
}

// ---------------- zsum ----------------
__global__ __launch_bounds__(512) void k_zsum2(const float* __restrict__ Wjm, int round0, int r){
    __shared__ __align__(16) float4 Ws4[64*16];
    __shared__ __align__(16) float4 Xs4[64*32];
    int s = blockIdx.x;
    int n0 = blockIdx.y*64;
    int tid = threadIdx.x;
    const float4* W4 = (const float4*)Wjm;
    #pragma unroll
    for (int i = tid; i < 1024; i += 512){
        int n = i >> 4, c = i & 15;
        Ws4[i] = W4[(size_t)(n0+n)*800 + c*50 + s];
    }
    #pragma unroll
    for (int i = tid; i < 2048; i += 512){
        int n = i >> 5, b = i & 31;
        float ga = round0 ? 0.02f : g_gamma[(size_t)(b*1024 + n0 + n)*50 + s];
        float4 sc = *(const float4*)&g_SC[(size_t)(b*1024 + n0 + n)*4];
        float4 x; x.x = ga*sc.x; x.y = ga*sc.y; x.z = ga*sc.z; x.w = ga*sc.w;
        Xs4[n*32 + b] = x;
    }
    __syncthreads();
    int c = tid & 15, b = tid >> 4;
    float acc = 0.f;
    #pragma unroll 8
    for (int n = 0; n < 64; n++){
        float4 w = Ws4[n*16 + c];
        float4 x = Xs4[n*32 + b];
        acc += w.x*x.x + w.y*x.y + w.z*x.z + w.w*x.w;
    }
    atomicAdd(&g_zs[r*NG*CS + b*CS + c*NCLS + s], acc);
}

// ---------------- fused: squash(zs[r]) inline + delta update + gamma ----------------
__global__ __launch_bounds__(512) void k_dg(const float* __restrict__ Wjm, int accum, int r){
    __shared__ __align__(16) float4 Ws4[800];
    __shared__ float sdel[1600];
    __shared__ float smx[32], siz[32];
    int n = blockIdx.x;
    int tid = threadIdx.x;
    const float4* W4 = (const float4*)Wjm + (size_t)n*800;
    for (int i = tid; i < 800; i += 512) Ws4[i] = W4[i];
    __syncthreads();
    for (int p = tid; p < 1600; p += 512){
        int b = p / 50, s = p % 50;
        const float* zsp = g_zs + r*NG*CS + b*CS + s;
        float zz[16]; float sqz = 0.f;
        #pragma unroll
        for (int c = 0; c < 16; c++){ float v = zsp[c*NCLS]; zz[c] = v; sqz += v*v; }
        float scz = sqz/(1.f+sqz)/(sqrtf(sqz + 1e-10f) + 1e-8f);
        float tx=0.f, ty=0.f, tz=0.f, tw=0.f;
        #pragma unroll
        for (int c = 0; c < 16; c++){
            float4 w = Ws4[c*50 + s];
            tx += w.x*zz[c]; ty += w.y*zz[c]; tz += w.z*zz[c]; tw += w.w*zz[c];
        }
        float4 sc = *(const float4*)&g_SC[(size_t)(b*1024 + n)*4];
        float d = (tx*sc.x + ty*sc.y + tz*sc.z + tw*sc.w) * scz;
        size_t o = (size_t)(b*1024 + n)*50 + s;
        if (accum) d += g_delta[o];
        g_delta[o] = d;
        sdel[p] = d;
    }
    __syncthreads();
    if (tid < 32){
        float m = -1e30f;
        for (int k=0;k<NCLS;k++) m = fmaxf(m, sdel[tid*50 + k]);
        float Z = 0.f;
        for (int k=0;k<NCLS;k++) Z += __expf(sdel[tid*50 + k] - m);
        smx[tid] = m; siz[tid] = 1.f/Z;
    }
    __syncthreads();
    for (int p = tid; p < 1600; p += 512){
        int b = p / 50;
        size_t o = (size_t)(b*1024 + n)*50 + (p % 50);
        g_gamma[o] = __expf(sdel[p] - smx[b]) * siz[b];
    }
}

// ---------------- final: z = squash(zs[2]) and logits ----------------
__global__ void k_zlogit(float* __restrict__ out){
    int b = blockIdx.x, s = threadIdx.x;
    if (s >= NCLS) return;
    float vals[DCCN]; float sq = 0.f;
    #pragma unroll
    for (int c=0;c<DCCN;c++){
        float v = g_zs[2*NG*CS + b*CS + c*NCLS + s]; vals[c]=v; sq += v*v;
    }
    float sc = sq/(1.f+sq)/(sqrtf(sq + 1e-10f) + 1e-8f);
    float sq2 = sq*sc*sc;
    float lg = sqrtf(sq2 + 1e-10f);
    out[b*NCLS + s] = lg;
    out[NG*NCLS + b*NCLS + s] = lg;
}

// ---------------- launch ----------------
extern "C" void kernel_launch(void* const* d_in, const int* in_sizes, int n_in,
                              void* d_out, int out_size){
    const int*   type_ids  = (const int*)  d_in[0];
    const int*   token_ids = (const int*)  d_in[1];
    const float* lw        = (const float*)d_in[4];
    const float* rw        = (const float*)d_in[5];
    const float* temb      = (const float*)d_in[7];
    const float* kemb      = (const float*)d_in[8];
    const float* WL        = (const float*)d_in[9];
    const float* WR        = (const float*)d_in[10];
    const float* WT        = (const float*)d_in[11];
    const float* bconv     = (const float*)d_in[12];
    const float* Wjm       = (const float*)d_in[13];
    float* out = (float*)d_out;

    k_embed<<<NN*32/256, 256>>>(type_ids, token_ids, temb, kemb);
    for (int l = 0; l < NLAY; l++)
        k_gemm<<<NPT/32, 256>>>(WL, WR, WT, bconv, lw, rw, l);
    k_top<<<NG, 1024>>>();
    k_vts<<<dim3(NG,8,1), 128>>>();
    // round 0 (gamma uniform = 1/50)
    k_zsum2<<<dim3(NCLS,16), 512>>>(Wjm, 1, 0);
    k_dg<<<NPG, 512>>>(Wjm, 0, 0);
    // round 1
    k_zsum2<<<dim3(NCLS,16), 512>>>(Wjm, 0, 1);
    k_dg<<<NPG, 512>>>(Wjm, 1, 1);
    // round 2 (final)
    k_zsum2<<<dim3(NCLS,16), 512>>>(Wjm, 0, 2);
    k_zlogit<<<NG, 64>>>(out);
}